// round 17
// baseline (speedup 1.0000x reference)
#include <cuda_runtime.h>
#include <math.h>
#include <stdint.h>

// Problem constants
#define BB 4
#define NN 4096
#define EE 131072
#define II 128
#define HH 128
#define FF 140

// ---------------- scratch (__device__ globals; no allocs allowed) ----------
__device__ float g_hm_sum[(size_t)BB * NN * HH];   // 8 MB
__device__ float g_pm_sum[(size_t)BB * NN * HH];   // 8 MB
__device__ float g_hr[(size_t)BB * NN * HH];       // hidden @ W1_top + b1
__device__ float g_hs[(size_t)BB * NN * HH];       // hidden @ W1_bot
__device__ int   g_cnt[NN];

// legacy-permuted tf32 weights: w[k][ (n%8)*16 + n/8 ]
__device__ float g_w1tp[128 * 128];   // msg_w1 rows 0..127   (recv half)
__device__ float g_w1bp[128 * 128];   // msg_w1 rows 128..255 (send half)
__device__ float g_w2p[128 * 128];
__device__ float g_pw1p[160 * 128];   // K padded 140 -> 160 with zeros
__device__ float g_pw2p[128 * 128];
// node weights: 0:res_w1 1:res_w2 2:ir_w 3:hr_w 4:ii_w 5:hi_w 6:in_w 7:hh_w 8:out_w1 9:out_w2 10:out_w3
__device__ float g_nw[11][128 * 128];

__device__ __forceinline__ float sigmoidf_(float x) {
    return 1.0f / (1.0f + expf(-x));
}

__device__ __forceinline__ unsigned rna(float x) {
    unsigned r;
    asm("cvt.rna.tf32.f32 %0, %1;" : "=r"(r) : "f"(x));
    return r;
}
__device__ __forceinline__ float uif(unsigned x) { return __uint_as_float(x); }

__device__ __forceinline__ void mma8(float* c,
                                     unsigned a0, unsigned a1, unsigned a2, unsigned a3,
                                     unsigned b0, unsigned b1) {
    asm volatile(
        "mma.sync.aligned.m16n8k8.row.col.f32.tf32.tf32.f32 "
        "{%0,%1,%2,%3}, {%4,%5,%6,%7}, {%8,%9}, {%0,%1,%2,%3};"
        : "+f"(c[0]), "+f"(c[1]), "+f"(c[2]), "+f"(c[3])
        : "r"(a0), "r"(a1), "r"(a2), "r"(a3), "r"(b0), "r"(b1));
}

__device__ __forceinline__ void red4(float* p, float4 v) {
    asm volatile("red.global.add.v4.f32 [%0], {%1,%2,%3,%4};"
                 :: "l"(p), "f"(v.x), "f"(v.y), "f"(v.z), "f"(v.w) : "memory");
}

__device__ __forceinline__ void cpa16(uint32_t dst_smem, const void* src) {
    asm volatile("cp.async.cg.shared.global [%0], [%1], 16;"
                 :: "r"(dst_smem), "l"(src) : "memory");
}
#define CP_COMMIT() asm volatile("cp.async.commit_group;" ::: "memory")
#define CP_WAIT0()  asm volatile("cp.async.wait_group 0;" ::: "memory")

// ---------------- helper kernels ----------------

__global__ void zero_kernel() {
    const size_t M = (size_t)BB * NN * HH;
    size_t stride = (size_t)gridDim.x * blockDim.x;
    size_t i = (size_t)blockIdx.x * blockDim.x + threadIdx.x;
    for (size_t j = i; j < M; j += stride) {
        g_hm_sum[j] = 0.0f;
        g_pm_sum[j] = 0.0f;
    }
    if (i < NN) g_cnt[i] = 0;
}

__global__ void count_kernel(const int* __restrict__ recv_e) {
    int e = blockIdx.x * blockDim.x + threadIdx.x;
    if (e < EE) atomicAdd(&g_cnt[recv_e[e]], 1);
}

__global__ void prep_kernel(const float* __restrict__ mw1,
                            const float* __restrict__ mw2,
                            const float* __restrict__ pw1,
                            const float* __restrict__ pw2,
                            const float* __restrict__ res_w1,
                            const float* __restrict__ res_w2,
                            const float* __restrict__ ir_w,
                            const float* __restrict__ hr_w,
                            const float* __restrict__ ii_w,
                            const float* __restrict__ hi_w,
                            const float* __restrict__ in_w,
                            const float* __restrict__ hh_w,
                            const float* __restrict__ out_w1,
                            const float* __restrict__ out_w2,
                            const float* __restrict__ out_w3) {
    int i = blockIdx.x * blockDim.x + threadIdx.x;   // up to 32768
    if (i < 128 * 128) {
        int k = i >> 7, n = i & 127;
        int s = k * 128 + ((n & 7) * 16 + (n >> 3));
        g_w1tp[s] = uif(rna(mw1[i]));                 // rows 0..127
        g_w1bp[s] = uif(rna(mw1[128 * 128 + i]));     // rows 128..255
        g_w2p[s]  = uif(rna(mw2[i]));
        g_pw2p[s] = uif(rna(pw2[i]));
        g_nw[0][s]  = uif(rna(res_w1[i]));
        g_nw[1][s]  = uif(rna(res_w2[i]));
        g_nw[2][s]  = uif(rna(ir_w[i]));
        g_nw[3][s]  = uif(rna(hr_w[i]));
        g_nw[4][s]  = uif(rna(ii_w[i]));
        g_nw[5][s]  = uif(rna(hi_w[i]));
        g_nw[6][s]  = uif(rna(in_w[i]));
        g_nw[7][s]  = uif(rna(hh_w[i]));
        g_nw[8][s]  = uif(rna(out_w1[i]));
        g_nw[9][s]  = uif(rna(out_w2[i]));
        g_nw[10][s] = uif(rna(out_w3[i]));
    }
    if (i < 160 * 128) {
        int k = i >> 7, n = i & 127;
        float v = (k < 140) ? pw1[i] : 0.0f;
        g_pw1p[k * 128 + ((n & 7) * 16 + (n >> 3))] = uif(rna(v));
    }
}

// ---------------- shared legacy-mma machinery (256-thread edge kernel) ------
#define EK_AB(buf)  ((buf) * (128 * 36))
#define EK_B(buf)   (128 * 132 + (buf) * (32 * 132))
#define EK_IDX      (128 * 132 + 2 * 32 * 132)
#define EK_SMEMF    (EK_IDX + 256)                    // 102,400 B

#define CHUNK_MMA(ACC, Ab, Ap, kofs, Bb, NKS)                                \
    {                                                                        \
        const unsigned* Au_ = (const unsigned*)(sm + (Ab));                  \
        const float4*   B4_ = (const float4*)(sm + (Bb));                    \
        _Pragma("unroll")                                                    \
        for (int ks = 0; ks < (NKS); ks++) {                                 \
            int kr = ks * 8;                                                 \
            int bb0 = (kr + q) * 33 + g * 4 + wn * 2;                        \
            int bb1 = (kr + q + 4) * 33 + g * 4 + wn * 2;                    \
            float4 u0 = B4_[bb0], u1 = B4_[bb0 + 1];                         \
            float4 v0 = B4_[bb1], v1 = B4_[bb1 + 1];                         \
            unsigned bu[8] = {__float_as_uint(u0.x), __float_as_uint(u0.y),  \
                              __float_as_uint(u0.z), __float_as_uint(u0.w),  \
                              __float_as_uint(u1.x), __float_as_uint(u1.y),  \
                              __float_as_uint(u1.z), __float_as_uint(u1.w)}; \
            unsigned bv[8] = {__float_as_uint(v0.x), __float_as_uint(v0.y),  \
                              __float_as_uint(v0.z), __float_as_uint(v0.w),  \
                              __float_as_uint(v1.x), __float_as_uint(v1.y),  \
                              __float_as_uint(v1.z), __float_as_uint(v1.w)}; \
            _Pragma("unroll")                                                \
            for (int t = 0; t < 2; t++) {                                    \
                int r0 = (m0 + t * 16 + g) * (Ap) + (kofs) + kr + q;         \
                unsigned a0 = Au_[r0], a1 = Au_[r0 + 8 * (Ap)];              \
                unsigned a2 = Au_[r0 + 4], a3 = Au_[r0 + 8 * (Ap) + 4];      \
                _Pragma("unroll")                                            \
                for (int j = 0; j < 8; j++)                                  \
                    mma8(ACC[t][j], a0, a1, a2, a3, bu[j], bv[j]);           \
            }                                                                \
        }                                                                    \
    }

#define ACC_INIT(ACC, BIAS)                                                  \
    _Pragma("unroll")                                                        \
    for (int j = 0; j < 8; j++) {                                            \
        int c0 = n0 + 8 * j + 2 * q;                                         \
        float b0v = __ldg((BIAS) + c0), b1v = __ldg((BIAS) + c0 + 1);        \
        _Pragma("unroll")                                                    \
        for (int t = 0; t < 2; t++) {                                        \
            ACC[t][j][0] = b0v; ACC[t][j][1] = b1v;                          \
            ACC[t][j][2] = b0v; ACC[t][j][3] = b1v;                          \
        }                                                                    \
    }

#define B_CPASYNC(dstbuf, WSRC)                                              \
    {                                                                        \
        const float4* wsrc_ = (WSRC);                                        \
        _Pragma("unroll")                                                    \
        for (int i = 0; i < 4; i++) {                                        \
            int it = tid + i * 256;                                          \
            int r = it >> 5, c = it & 31;                                    \
            cpa16(smem_u32 + (uint32_t)((EK_B(dstbuf) + r * 132 + c * 4) * 4), \
                  wsrc_ + r * 32 + c);                                       \
        }                                                                    \
        CP_COMMIT();                                                         \
    }

// ---------------- 512-thread gemm machinery (node, hm_pre) ------------------
#define NACC_INIT(ACC, BIAS)                                                 \
    _Pragma("unroll")                                                        \
    for (int j = 0; j < 8; j++) {                                            \
        float b0v = 0.0f, b1v = 0.0f;                                        \
        if (BIAS) {                                                          \
            int c0 = n0 + 8 * j + 2 * q;                                     \
            b0v = __ldg((const float*)(BIAS) + c0);                          \
            b1v = __ldg((const float*)(BIAS) + c0 + 1);                      \
        }                                                                    \
        ACC[j][0] = b0v; ACC[j][1] = b1v;                                    \
        ACC[j][2] = b0v; ACC[j][3] = b1v;                                    \
    }

__device__ __forceinline__ void gemm128v(const float* As, const float* Wg, float* sB,
                                         float acc[8][4], int tid) {
    const int wid = tid >> 5, lane = tid & 31;
    const int wm = wid >> 1, wn = wid & 1;
    const int m0 = wm * 16;
    const int g = lane >> 2, q = lane & 3;

    #pragma unroll 1
    for (int c2 = 0; c2 < 4; c2++) {
        __syncthreads();
        const float4* wsrc = (const float4*)Wg + c2 * 32 * 32;
        #pragma unroll
        for (int i = 0; i < 2; i++) {
            int it = tid + i * 512;
            int r = it >> 5, c = it & 31;
            *(float4*)(sB + r * 132 + c * 4) = wsrc[r * 32 + c];
        }
        __syncthreads();

        const unsigned* Mu = (const unsigned*)As;
        const float4*   B4 = (const float4*)sB;
        #pragma unroll
        for (int ks = 0; ks < 4; ks++) {
            int kr = ks * 8;
            int bb0 = (kr + q) * 33 + g * 4 + wn * 2;
            int bb1 = (kr + q + 4) * 33 + g * 4 + wn * 2;
            float4 u0 = B4[bb0], u1 = B4[bb0 + 1];
            float4 v0 = B4[bb1], v1 = B4[bb1 + 1];
            unsigned bu[8] = {__float_as_uint(u0.x), __float_as_uint(u0.y),
                              __float_as_uint(u0.z), __float_as_uint(u0.w),
                              __float_as_uint(u1.x), __float_as_uint(u1.y),
                              __float_as_uint(u1.z), __float_as_uint(u1.w)};
            unsigned bv[8] = {__float_as_uint(v0.x), __float_as_uint(v0.y),
                              __float_as_uint(v0.z), __float_as_uint(v0.w),
                              __float_as_uint(v1.x), __float_as_uint(v1.y),
                              __float_as_uint(v1.z), __float_as_uint(v1.w)};
            int r0 = (m0 + g) * 132 + c2 * 32 + kr + q;
            unsigned a0 = Mu[r0], a1 = Mu[r0 + 8 * 132];
            unsigned a2 = Mu[r0 + 4], a3 = Mu[r0 + 8 * 132 + 4];
            #pragma unroll
            for (int j = 0; j < 8; j++) mma8(acc[j], a0, a1, a2, a3, bu[j], bv[j]);
        }
    }
    __syncthreads();
}

// ---------------- hm_pre: H_r = hidden@W1_top + b1 ; H_s = hidden@W1_bot ----
#define HP_X 0
#define HP_B (128 * 132)
#define HP_SMEMF (HP_B + 32 * 132)     // 84,480 B

__global__ void __launch_bounds__(512) hm_pre_kernel(
    const float* __restrict__ hidden,
    const float* __restrict__ mb1)
{
    extern __shared__ __align__(16) float sm[];
    float* s_x = sm + HP_X;
    float* s_B = sm + HP_B;

    const int tid  = threadIdx.x;
    const int row0 = blockIdx.x * 128;   // linear row in [0, BB*NN)

    #pragma unroll
    for (int i = 0; i < 8; i++) {
        int it = tid + i * 512;
        int r = it >> 5, c4v = it & 31;
        float4 h = *(const float4*)(hidden + (size_t)(row0 + r) * HH + c4v * 4);
        uint4 x; x.x = rna(h.x); x.y = rna(h.y); x.z = rna(h.z); x.w = rna(h.w);
        *(uint4*)(s_x + r * 132 + c4v * 4) = x;
    }

    const int wid = tid >> 5, lane = tid & 31;
    const int wm = wid >> 1, wn = wid & 1;
    const int m0 = wm * 16, n0 = wn * 64;
    const int g = lane >> 2, q = lane & 3;

    float acc[8][4];

    // H_r = x @ W1_top + b1
    NACC_INIT(acc, mb1)
    gemm128v(s_x, g_w1tp, s_B, acc, tid);
    {
        int r_ = m0 + g;
        #pragma unroll
        for (int j = 0; j < 8; j++) {
            int c0 = n0 + 8 * j + 2 * q;
            float2 p0, p2;
            p0.x = acc[j][0]; p0.y = acc[j][1];
            p2.x = acc[j][2]; p2.y = acc[j][3];
            *(float2*)(g_hr + (size_t)(row0 + r_) * HH + c0) = p0;
            *(float2*)(g_hr + (size_t)(row0 + r_ + 8) * HH + c0) = p2;
        }
    }

    // H_s = x @ W1_bot
    NACC_INIT(acc, (const float*)nullptr)
    gemm128v(s_x, g_w1bp, s_B, acc, tid);
    {
        int r_ = m0 + g;
        #pragma unroll
        for (int j = 0; j < 8; j++) {
            int c0 = n0 + 8 * j + 2 * q;
            float2 p0, p2;
            p0.x = acc[j][0]; p0.y = acc[j][1];
            p2.x = acc[j][2]; p2.y = acc[j][3];
            *(float2*)(g_hs + (size_t)(row0 + r_) * HH + c0) = p0;
            *(float2*)(g_hs + (size_t)(row0 + r_ + 8) * HH + c0) = p2;
        }
    }
}

// ---------------- fused edge kernel: hm path (x<1024) | pm path (x>=1024) ---
__global__ void __launch_bounds__(256, 2) edge_kernel(
    const float* __restrict__ edge_attr,
    const int* __restrict__ send_e, const int* __restrict__ recv_e,
    const float* __restrict__ mb2,
    const float* __restrict__ pb1, const float* __restrict__ pb2)
{
    extern __shared__ __align__(16) float sm[];
    const int tid = threadIdx.x;
    const int b   = blockIdx.y;
    const uint32_t smem_u32 = (uint32_t)__cvta_generic_to_shared(sm);

    const int warp = tid >> 5, lane = tid & 31;
    const int wm = warp >> 1, wn = warp & 1;
    const int m0 = wm * 32, n0 = wn * 64;
    const int g = lane >> 2, q = lane & 3;

    if (blockIdx.x < 1024) {
        // =============== hm path (factored layer 1 + pipelined layer 2) =====
        int* s_recv = (int*)(sm + EK_IDX);
        int* s_send = s_recv + 128;
        const int e0 = blockIdx.x * 128;

        if (tid < 128) s_recv[tid] = recv_e[e0 + tid];
        else           s_send[tid - 128] = send_e[e0 + tid - 128];

        const int se = tid >> 1, half = (tid & 1) * 16;

        float acc2[2][8][4];
        ACC_INIT(acc2, mb2)
        __syncthreads();   // idx visible

        const float* hr = g_hr + (size_t)b * NN * HH;
        const float* hs = g_hs + (size_t)b * NN * HH;
        const float* pr_base = hr + (size_t)s_recv[se] * HH + half;
        const float* ps_base = hs + (size_t)s_send[se] * HH + half;

        {
            B_CPASYNC(0, (const float4*)g_w2p)
            #pragma unroll
            for (int v = 0; v < 4; v++) {
                float4 a = *(const float4*)(pr_base + v * 4);
                float4 c = *(const float4*)(ps_base + v * 4);
                uint4 r;
                r.x = rna(tanhf(a.x + c.x));
                r.y = rna(tanhf(a.y + c.y));
                r.z = rna(tanhf(a.z + c.z));
                r.w = rna(tanhf(a.w + c.w));
                *(uint4*)(sm + EK_AB(0) + se * 36 + half + v * 4) = r;
            }
            CP_WAIT0();
        }
        __syncthreads();

        #pragma unroll 1
        for (int c2 = 0; c2 < 4; c2++) {
            const int cur = c2 & 1, nxt = cur ^ 1;
            const bool has = (c2 + 1) < 4;
            float4 pr4[4], ps4[4];
            if (has) {
                const int k0 = (c2 + 1) * 32;
                #pragma unroll
                for (int v = 0; v < 4; v++) {
                    pr4[v] = *(const float4*)(pr_base + k0 + v * 4);
                    ps4[v] = *(const float4*)(ps_base + k0 + v * 4);
                }
                B_CPASYNC(nxt, (const float4*)g_w2p + (c2 + 1) * 32 * 32)
            }
            CHUNK_MMA(acc2, EK_AB(cur), 36, 0, EK_B(cur), 4)
            if (has) {
                #pragma unroll
                for (int v = 0; v < 4; v++) {
                    uint4 r;
                    r.x = rna(tanhf(pr4[v].x + ps4[v].x));
                    r.y = rna(tanhf(pr4[v].y + ps4[v].y));
                    r.z = rna(tanhf(pr4[v].z + ps4[v].z));
                    r.w = rna(tanhf(pr4[v].w + ps4[v].w));
                    *(uint4*)(sm + EK_AB(nxt) + se * 36 + half + v * 4) = r;
                }
                CP_WAIT0();
            }
            __syncthreads();
        }

        #pragma unroll
        for (int t = 0; t < 2; t++) {
            int r = m0 + t * 16 + g;
            #pragma unroll
            for (int j = 0; j < 8; j++) {
                int c0 = n0 + 8 * j + 2 * q;
                sm[r * 132 + c0]           = tanhf(acc2[t][j][0]);
                sm[r * 132 + c0 + 1]       = tanhf(acc2[t][j][1]);
                sm[(r + 8) * 132 + c0]     = tanhf(acc2[t][j][2]);
                sm[(r + 8) * 132 + c0 + 1] = tanhf(acc2[t][j][3]);
            }
        }
        __syncthreads();

        float* dst = g_hm_sum + (size_t)b * NN * HH;
        const int c4 = tid & 31;
        #pragma unroll 1
        for (int e = tid >> 5; e < 128; e += 8) {
            float4 v = *(const float4*)(sm + e * 132 + c4 * 4);
            red4(dst + (size_t)s_recv[e] * HH + c4 * 4, v);
        }
    } else {
        // =============== pm path (pipelined, K=144 with K=16 tail) ==========
        int* s_recv = (int*)(sm + EK_IDX);
        const int e0 = (blockIdx.x - 1024) * 128;

        if (tid < 128) s_recv[tid] = recv_e[e0 + tid];

        const int se = tid >> 3, sv = tid & 7;

        float acc[2][8][4];
        ACC_INIT(acc, pb1)

        const float* ea = edge_attr + ((size_t)b * EE + e0) * FF;

        {
            #pragma unroll
            for (int i = 0; i < 4; i++) {
                int e = se + i * 32;
                int f = sv * 4;
                float4 fv = *(const float4*)(ea + (size_t)e * FF + f);
                uint4 r; r.x = rna(fv.x); r.y = rna(fv.y); r.z = rna(fv.z); r.w = rna(fv.w);
                *(uint4*)(sm + EK_AB(0) + e * 36 + sv * 4) = r;
            }
            B_CPASYNC(0, (const float4*)g_pw1p)
            CP_WAIT0();
        }
        __syncthreads();

        #pragma unroll 1
        for (int kc = 0; kc < 4; kc++) {
            const int cur = kc & 1, nxt = cur ^ 1;
            float4 pf[4];
            {
                const int k0 = (kc + 1) * 32;
                #pragma unroll
                for (int i = 0; i < 4; i++) {
                    int e = se + i * 32;
                    int f = k0 + sv * 4;
                    if (f < FF) pf[i] = *(const float4*)(ea + (size_t)e * FF + f);
                    else { pf[i].x = 0.0f; pf[i].y = 0.0f; pf[i].z = 0.0f; pf[i].w = 0.0f; }
                }
                B_CPASYNC(nxt, (const float4*)g_pw1p + (kc + 1) * 32 * 32)
            }
            CHUNK_MMA(acc, EK_AB(cur), 36, 0, EK_B(cur), 4)
            {
                #pragma unroll
                for (int i = 0; i < 4; i++) {
                    int e = se + i * 32;
                    uint4 r;
                    r.x = rna(pf[i].x); r.y = rna(pf[i].y);
                    r.z = rna(pf[i].z); r.w = rna(pf[i].w);
                    *(uint4*)(sm + EK_AB(nxt) + e * 36 + sv * 4) = r;
                }
                CP_WAIT0();
            }
            __syncthreads();
        }

        // tail chunk: K=16 only (cols 128..143; rest is zero padding)
        CHUNK_MMA(acc, EK_AB(0), 36, 0, EK_B(0), 2)
        __syncthreads();

        B_CPASYNC(0, (const float4*)g_pw2p)
        #pragma unroll
        for (int t = 0; t < 2; t++) {
            int r = m0 + t * 16 + g;
            #pragma unroll
            for (int j = 0; j < 8; j++) {
                int c0 = n0 + 8 * j + 2 * q;
                sm[r * 132 + c0]           = uif(rna(fmaxf(acc[t][j][0], 0.0f)));
                sm[r * 132 + c0 + 1]       = uif(rna(fmaxf(acc[t][j][1], 0.0f)));
                sm[(r + 8) * 132 + c0]     = uif(rna(fmaxf(acc[t][j][2], 0.0f)));
                sm[(r + 8) * 132 + c0 + 1] = uif(rna(fmaxf(acc[t][j][3], 0.0f)));
            }
        }
        float acc2[2][8][4];
        ACC_INIT(acc2, pb2)
        CP_WAIT0();
        __syncthreads();

        #pragma unroll 1
        for (int c2 = 0; c2 < 4; c2++) {
            const int cur = c2 & 1, nxt = cur ^ 1;
            const bool has = (c2 + 1) < 4;
            if (has) B_CPASYNC(nxt, (const float4*)g_pw2p + (c2 + 1) * 32 * 32)
            CHUNK_MMA(acc2, 0, 132, c2 * 32, EK_B(cur), 4)
            if (has) CP_WAIT0();
            __syncthreads();
        }

        #pragma unroll
        for (int t = 0; t < 2; t++) {
            int r = m0 + t * 16 + g;
            #pragma unroll
            for (int j = 0; j < 8; j++) {
                int c0 = n0 + 8 * j + 2 * q;
                sm[r * 132 + c0]           = fmaxf(acc2[t][j][0], 0.0f);
                sm[r * 132 + c0 + 1]       = fmaxf(acc2[t][j][1], 0.0f);
                sm[(r + 8) * 132 + c0]     = fmaxf(acc2[t][j][2], 0.0f);
                sm[(r + 8) * 132 + c0 + 1] = fmaxf(acc2[t][j][3], 0.0f);
            }
        }
        __syncthreads();

        float* dst = g_pm_sum + (size_t)b * NN * HH;
        const int c4 = tid & 31;
        #pragma unroll 1
        for (int e = tid >> 5; e < 128; e += 8) {
            float4 v = *(const float4*)(sm + e * 132 + c4 * 4);
            red4(dst + (size_t)s_recv[e] * HH + c4 * 4, v);
        }
    }
}

// ---------------- node kernel (tf32, 512 threads / 16 warps) ----------------
#define ND_PRES 0
#define ND_HEMB (128 * 132)
#define ND_X    (2 * 128 * 132)
#define ND_B    (3 * 128 * 132)
#define ND_SMEMF (ND_B + 32 * 132)

__global__ void __launch_bounds__(512) node_kernel(
    const float* __restrict__ inputs,
    const float* __restrict__ hidden,
    const float* __restrict__ res_b1, const float* __restrict__ res_b2,
    const float* __restrict__ ir_b,   const float* __restrict__ ii_b,
    const float* __restrict__ in_b,
    const float* __restrict__ out_b1, const float* __restrict__ out_b2,
    const float* __restrict__ out_b3,
    float* __restrict__ out_pred,
    float* __restrict__ out_hidden)
{
    extern __shared__ __align__(16) float sm[];
    float* s_pres = sm + ND_PRES;
    float* s_hemb = sm + ND_HEMB;
    float* s_x    = sm + ND_X;
    float* s_B    = sm + ND_B;

    const int tid  = threadIdx.x;
    const int row0 = blockIdx.x * 128;

    #pragma unroll
    for (int i = 0; i < 8; i++) {
        int it = tid + i * 512;
        int r = it >> 5, c4v = it & 31;
        size_t off = (size_t)(row0 + r) * HH + c4v * 4;
        float invc = 1.0f / fmaxf((float)__ldg(&g_cnt[(row0 + r) & (NN - 1)]), 1.0f);
        float4 hm4 = *(const float4*)(g_hm_sum + off);
        float4 pm4 = *(const float4*)(g_pm_sum + off);
        float4 in4 = *(const float4*)(inputs + off);
        uint4 a;
        a.x = rna(hm4.x * invc); a.y = rna(hm4.y * invc);
        a.z = rna(hm4.z * invc); a.w = rna(hm4.w * invc);
        *(uint4*)(s_hemb + r * 132 + c4v * 4) = a;
        float4 p;
        p.x = pm4.x * invc; p.y = pm4.y * invc; p.z = pm4.z * invc; p.w = pm4.w * invc;
        *(float4*)(s_pres + r * 132 + c4v * 4) = p;
        uint4 x;
        x.x = rna(in4.x); x.y = rna(in4.y); x.z = rna(in4.z); x.w = rna(in4.w);
        *(uint4*)(s_x + r * 132 + c4v * 4) = x;
    }

    const int wid = tid >> 5, lane = tid & 31;
    const int wm = wid >> 1, wn = wid & 1;
    const int m0 = wm * 16, n0 = wn * 64;
    const int g = lane >> 2, q = lane & 3;
    (void)wn;

    float acc[8][4];

    #define NFRAG_LOOP(...)                                              \
        {                                                                \
            int r_ = m0 + g;                                             \
            _Pragma("unroll")                                            \
            for (int j = 0; j < 8; j++) {                                \
                int c0 = n0 + 8 * j + 2 * q;                             \
                int i0 = r_ * 132 + c0;                                  \
                int i2 = (r_ + 8) * 132 + c0;                            \
                (void)i0; (void)i2;                                      \
                __VA_ARGS__                                              \
            }                                                            \
        }

    NACC_INIT(acc, res_b1)
    gemm128v(s_x, g_nw[0], s_B, acc, tid);
    NFRAG_LOOP({
        s_x[i0]     = uif(rna(fmaxf(acc[j][0], 0.0f)));
        s_x[i0 + 1] = uif(rna(fmaxf(acc[j][1], 0.0f)));
        s_x[i2]     = uif(rna(fmaxf(acc[j][2], 0.0f)));
        s_x[i2 + 1] = uif(rna(fmaxf(acc[j][3], 0.0f)));
    })

    NACC_INIT(acc, res_b2)
    gemm128v(s_x, g_nw[1], s_B, acc, tid);
    NFRAG_LOOP({
        s_pres[i0]     = uif(rna(fmaxf(acc[j][0], 0.0f) + s_pres[i0]));
        s_pres[i0 + 1] = uif(rna(fmaxf(acc[j][1], 0.0f) + s_pres[i0 + 1]));
        s_pres[i2]     = uif(rna(fmaxf(acc[j][2], 0.0f) + s_pres[i2]));
        s_pres[i2 + 1] = uif(rna(fmaxf(acc[j][3], 0.0f) + s_pres[i2 + 1]));
    })

    NACC_INIT(acc, (const float*)nullptr)
    gemm128v(s_hemb, g_nw[7], s_B, acc, tid);
    NFRAG_LOOP({
        s_x[i0]     = acc[j][0];
        s_x[i0 + 1] = acc[j][1];
        s_x[i2]     = acc[j][2];
        s_x[i2 + 1] = acc[j][3];
    })

    NACC_INIT(acc, ir_b)
    gemm128v(s_pres, g_nw[2], s_B, acc, tid);
    gemm128v(s_hemb, g_nw[3], s_B, acc, tid);
    NFRAG_LOOP({
        s_x[i0]     = sigmoidf_(acc[j][0]) * s_x[i0];
        s_x[i0 + 1] = sigmoidf_(acc[j][1]) * s_x[i0 + 1];
        s_x[i2]     = sigmoidf_(acc[j][2]) * s_x[i2];
        s_x[i2 + 1] = sigmoidf_(acc[j][3]) * s_x[i2 + 1];
    })

    NACC_INIT(acc, ii_b)
    gemm128v(s_pres, g_nw[4], s_B, acc, tid);
    gemm128v(s_hemb, g_nw[5], s_B, acc, tid);
    NFRAG_LOOP({
        s_hemb[i0]     = sigmoidf_(acc[j][0]);
        s_hemb[i0 + 1] = sigmoidf_(acc[j][1]);
        s_hemb[i2]     = sigmoidf_(acc[j][2]);
        s_hemb[i2 + 1] = sigmoidf_(acc[j][3]);
    })

    NACC_INIT(acc, in_b)
    gemm128v(s_pres, g_nw[6], s_B, acc, tid);
    NFRAG_LOOP({
        float n_0 = tanhf(acc[j][0] + s_x[i0]);
        float n_1 = tanhf(acc[j][1] + s_x[i0 + 1]);
        float n_2 = tanhf(acc[j][2] + s_x[i2]);
        float n_3 = tanhf(acc[j][3] + s_x[i2 + 1]);
        float i_0 = s_hemb[i0];
        float i_1 = s_hemb[i0 + 1];
        float i_2 = s_hemb[i2];
        float i_3 = s_hemb[i2 + 1];
        size_t go0 = (size_t)(row0 + r_) * HH + c0;
        size_t go2 = (size_t)(row0 + r_ + 8) * HH + c0;
        float2 h0 = *(const float2*)(hidden + go0);
        float2 h2 = *(const float2*)(hidden + go2);
        float2 nh0;
        float2 nh2;
        nh0.x = (1.0f - i_0) * n_0 + i_0 * h0.x;
        nh0.y = (1.0f - i_1) * n_1 + i_1 * h0.y;
        nh2.x = (1.0f - i_2) * n_2 + i_2 * h2.x;
        nh2.y = (1.0f - i_3) * n_3 + i_3 * h2.y;
        *(float2*)(out_hidden + go0) = nh0;
        *(float2*)(out_hidden + go2) = nh2;
        s_x[i0]     = uif(rna(nh0.x));
        s_x[i0 + 1] = uif(rna(nh0.y));
        s_x[i2]     = uif(rna(nh2.x));
        s_x[i2 + 1] = uif(rna(nh2.y));
    })

    NACC_INIT(acc, out_b1)
    gemm128v(s_x, g_nw[8], s_B, acc, tid);
    NFRAG_LOOP({
        s_hemb[i0]     = uif(rna(fmaxf(acc[j][0], 0.0f)));
        s_hemb[i0 + 1] = uif(rna(fmaxf(acc[j][1], 0.0f)));
        s_hemb[i2]     = uif(rna(fmaxf(acc[j][2], 0.0f)));
        s_hemb[i2 + 1] = uif(rna(fmaxf(acc[j][3], 0.0f)));
    })

    NACC_INIT(acc, out_b2)
    gemm128v(s_hemb, g_nw[9], s_B, acc, tid);
    NFRAG_LOOP({
        s_x[i0]     = uif(rna(fmaxf(acc[j][0], 0.0f)));
        s_x[i0 + 1] = uif(rna(fmaxf(acc[j][1], 0.0f)));
        s_x[i2]     = uif(rna(fmaxf(acc[j][2], 0.0f)));
        s_x[i2 + 1] = uif(rna(fmaxf(acc[j][3], 0.0f)));
    })

    NACC_INIT(acc, out_b3)
    gemm128v(s_x, g_nw[10], s_B, acc, tid);
    NFRAG_LOOP({
        size_t go0 = (size_t)(row0 + r_) * II + c0;
        size_t go2 = (size_t)(row0 + r_ + 8) * II + c0;
        float2 p0;
        float2 p2;
        p0.x = acc[j][0]; p0.y = acc[j][1];
        p2.x = acc[j][2]; p2.y = acc[j][3];
        *(float2*)(out_pred + go0) = p0;
        *(float2*)(out_pred + go2) = p2;
    })
    #undef NFRAG_LOOP
}

// ---------------- launch ----------------
extern "C" void kernel_launch(void* const* d_in, const int* in_sizes, int n_in,
                              void* d_out, int out_size) {
    const float* inputs    = (const float*)d_in[0];
    const float* edge_attr = (const float*)d_in[1];
    const int*   send_e    = (const int*)  d_in[2];
    const int*   recv_e    = (const int*)  d_in[3];
    const float* hidden    = (const float*)d_in[4];
    const float* msg_w1 = (const float*)d_in[5];
    const float* msg_b1 = (const float*)d_in[6];
    const float* msg_w2 = (const float*)d_in[7];
    const float* msg_b2 = (const float*)d_in[8];
    const float* pm_w1  = (const float*)d_in[9];
    const float* pm_b1  = (const float*)d_in[10];
    const float* pm_w2  = (const float*)d_in[11];
    const float* pm_b2  = (const float*)d_in[12];
    const float* res_w1 = (const float*)d_in[13];
    const float* res_b1 = (const float*)d_in[14];
    const float* res_w2 = (const float*)d_in[15];
    const float* res_b2 = (const float*)d_in[16];
    const float* ir_w   = (const float*)d_in[17];
    const float* ir_b   = (const float*)d_in[18];
    const float* ii_w   = (const float*)d_in[19];
    const float* ii_b   = (const float*)d_in[20];
    const float* in_w   = (const float*)d_in[21];
    const float* in_b   = (const float*)d_in[22];
    const float* hr_w   = (const float*)d_in[23];
    const float* hi_w   = (const float*)d_in[24];
    const float* hh_w   = (const float*)d_in[25];
    const float* out_w1 = (const float*)d_in[26];
    const float* out_b1 = (const float*)d_in[27];
    const float* out_w2 = (const float*)d_in[28];
    const float* out_b2 = (const float*)d_in[29];
    const float* out_w3 = (const float*)d_in[30];
    const float* out_b3 = (const float*)d_in[31];

    float* out_pred   = (float*)d_out;
    float* out_hidden = (float*)d_out + (size_t)BB * NN * II;

    const int EK_SMEM = EK_SMEMF * 4;     // 102,400 B -> 2 CTAs/SM
    const int HP_SMEM = HP_SMEMF * 4;     //  84,480 B
    const int ND_SMEM = ND_SMEMF * 4;     // 219,648 B
    cudaFuncSetAttribute(edge_kernel, cudaFuncAttributeMaxDynamicSharedMemorySize, EK_SMEM);
    cudaFuncSetAttribute(hm_pre_kernel, cudaFuncAttributeMaxDynamicSharedMemorySize, HP_SMEM);
    cudaFuncSetAttribute(node_kernel, cudaFuncAttributeMaxDynamicSharedMemorySize, ND_SMEM);

    zero_kernel<<<1024, 256>>>();
    count_kernel<<<EE / 256, 256>>>(recv_e);
    prep_kernel<<<128, 256>>>(msg_w1, msg_w2, pm_w1, pm_w2,
                              res_w1, res_w2, ir_w, hr_w, ii_w, hi_w,
                              in_w, hh_w, out_w1, out_w2, out_w3);

    hm_pre_kernel<<<(BB * NN) / 128, 512, HP_SMEM>>>(hidden, msg_b1);
    edge_kernel<<<dim3(2048, BB), 256, EK_SMEM>>>(edge_attr, send_e, recv_e,
                                                  msg_b2, pm_b1, pm_b2);

    node_kernel<<<(BB * NN) / 128, 512, ND_SMEM>>>(
        inputs, hidden,
        res_b1, res_b2, ir_b, ii_b, in_b,
        out_b1, out_b2, out_b3,
        out_pred, out_hidden);
}